// round 11
// baseline (speedup 1.0000x reference)
#include <cuda_runtime.h>
#include <cstdint>

#define Nn 4
#define Mm 1024
#define Dd 64
#define Ll 16
#define Bb 4096
#define BL 65536
#define DECAYF 0.999f
#define EPSF 1e-5f
#define COMMITF 0.05f

#define OFF_ZQ   0LL
#define OFF_LOSS 16777216LL
#define OFF_PERP 16777217LL
#define OFF_IDX  16777218LL
#define OFF_EZQ  17039362LL
#define OFF_EMB  33816578LL
#define OFF_CNT  34078722LL
#define OFF_EMW  34082818LL

__device__ float g_xt[Nn * BL * Dd];      // x (n, k, d) row-major
__device__ float g_xtT[Nn * Dd * BL];     // x transposed (n, d, k)
__device__ float g_etT[Nn * Dd * Mm];     // embedding transposed (n, d, m)
__device__ float g_xnorm[Nn * BL];
__device__ int   g_idx[Nn * BL];
__device__ float g_dw[Nn * Mm * Dd];
__device__ int   g_cnt[Nn * Mm];
__device__ float g_enorm[Nn * Mm];
__device__ float g_fcnt[Nn * Mm];
__device__ float g_losspart[Bb * Nn];

#define CP_ASYNC16(dst, src) \
    asm volatile("cp.async.cg.shared.global [%0], [%1], 16;" :: "r"(dst), "l"(src))
#define CP_COMMIT() asm volatile("cp.async.commit_group;" ::: "memory")
#define CP_WAIT(nconst) asm volatile("cp.async.wait_group %0;" :: "n"(nconst) : "memory")

// packed dual-fp32 FMA (each lane IEEE fp32 -> bit-exact per-element chain)
#define FMA2(acc, a, b) \
    asm("fma.rn.f32x2 %0, %1, %2, %0;" : "+l"(acc) : "l"(a), "l"(b))
#define DUP2(dst, f) \
    asm("mov.b64 %0, {%1, %1};" : "=l"(dst) : "r"(__float_as_uint(f)))

__device__ __forceinline__ uint32_t smem_u32(const void* p) {
    uint32_t a;
    asm("{ .reg .u64 t; cvta.to.shared.u64 t, %1; cvt.u32.u64 %0, t; }" : "=r"(a) : "l"(p));
    return a;
}
__device__ __forceinline__ unsigned long long minull(unsigned long long a, unsigned long long b) {
    return a < b ? a : b;
}

// ---------------------------------------------------------------------------
__global__ void k_zero() {
    int i = blockIdx.x * 256 + threadIdx.x;
    if (i < Nn * Mm * Dd) g_dw[i] = 0.0f;
    if (i < Nn * Mm)      g_cnt[i] = 0;
}

// ---------------------------------------------------------------------------
// Transpose x -> g_xt (row-major) + g_xtT (d-major); ||x||^2 reference-rounded.
__global__ void k_transpose(const float* __restrict__ x) {
    __shared__ float s[16][65];
    int bn = blockIdx.x;
    int b = bn >> 2, n = bn & 3;
    int t = threadIdx.x;
    const float4* xp = (const float4*)(x + (long long)b * 4096 + n * 1024);
    float4 v = xp[t];
    int d = t >> 2, lb = (t & 3) * 4;
    s[lb + 0][d] = v.x; s[lb + 1][d] = v.y; s[lb + 2][d] = v.z; s[lb + 3][d] = v.w;
    __syncthreads();
    int r = t >> 4, c = t & 15;
    float4 w = make_float4(s[r][c * 4], s[r][c * 4 + 1], s[r][c * 4 + 2], s[r][c * 4 + 3]);
    size_t row = (size_t)n * BL + b * 16 + r;
    ((float4*)g_xt)[row * 16 + c] = w;
    int dd = t >> 2, l4 = (t & 3) * 4;
    size_t tb = ((size_t)n * 64 + dd) * BL + b * 16 + l4;
    g_xtT[tb + 0] = s[l4 + 0][dd];
    g_xtT[tb + 1] = s[l4 + 1][dd];
    g_xtT[tb + 2] = s[l4 + 2][dd];
    g_xtT[tb + 3] = s[l4 + 3][dd];
    if (t < 16) {
        float acc = 0.0f;
        #pragma unroll 8
        for (int d2 = 0; d2 < 64; d2++) {
            float vv = s[t][d2];
            acc = __fadd_rn(acc, __fmul_rn(vv, vv));
        }
        g_xnorm[(size_t)n * BL + b * 16 + t] = acc;
    }
}

// ---------------------------------------------------------------------------
__global__ void k_enorm(const float* __restrict__ emb) {
    int i = blockIdx.x * blockDim.x + threadIdx.x;   // 0..4095
    const float* e = emb + (size_t)i * 64;
    float s = 0.0f;
    #pragma unroll 8
    for (int d = 0; d < 64; d++) {
        float v = e[d];
        s = __fadd_rn(s, __fmul_rn(v, v));
    }
    g_enorm[i] = s;
}

// ---------------------------------------------------------------------------
// Embedding transpose: g_etT[n][d][m]. grid (16, 4), 256 thr, 64m x 64d tile.
__global__ void k_et(const float* __restrict__ emb) {
    __shared__ float sm[64][65];
    int n = blockIdx.y, mbase = blockIdx.x * 64;
    int t = threadIdx.x;
    #pragma unroll
    for (int i = 0; i < 16; i++) {
        int idx = t + i * 256;
        sm[idx >> 6][idx & 63] = emb[((size_t)n * Mm + mbase + (idx >> 6)) * 64 + (idx & 63)];
    }
    __syncthreads();
    #pragma unroll
    for (int i = 0; i < 16; i++) {
        int idx = t + i * 256;
        g_etT[((size_t)n * 64 + (idx >> 6)) * Mm + mbase + (idx & 63)] = sm[idx & 63][idx >> 6];
    }
}

// ---------------------------------------------------------------------------
// FFMA2 argmin, double-buffered 64-m tiles, register argmin keys.
// 256 threads (tx=t&31 covers 2 m each; ty=t>>5 warp owns 16 k-rows).
// CTA: 128 k-rows, 16 m-tiles of 64 codes. Bit-exact reference score:
//   score = fl( fl(Sx + Se) - 2*dot ), dot = ascending-d fma chain (FMA2 lanes).
#define XTS 132                       // xt row stride (floats)
#define ETS 68                        // est row stride (floats)
#define SMO_ENS 0                     // 1024 f
#define SMO_XNR 1024                  // 128 f
#define SMO_XT  1152                  // 64*132 = 8448 f
#define SMO_EST 9600                  // 2 buffers of 64*68 = 4352 f
#define SM_TOTF (9600 + 2 * 64 * ETS) // 18304 f
#define SM_BYTES (SM_TOTF * 4)        // 73216 B

extern __shared__ float smf[];
__global__ void __launch_bounds__(256, 2)
k_argmin(float* __restrict__ out) {
    const int n = blockIdx.y;
    const int kbase = blockIdx.x * 128;
    const int t = threadIdx.x;
    const int tx = t & 31, ty = t >> 5;
    float* ens = smf + SMO_ENS;
    float* xnr = smf + SMO_XNR;
    float* xt  = smf + SMO_XT;
    uint32_t sb = smem_u32(smf);

    const float* gx = g_xtT + (size_t)n * 64 * BL;
    const float* ge = g_etT + (size_t)n * 64 * Mm;

    // group 0: xt tile (64d x 128k) + est tile 0; group 1: est tile 1
    #pragma unroll
    for (int i = 0; i < 8; i++) {
        int idx = t + i * 256;                   // 2048 chunks, row=idx>>5, c=idx&31
        int row = idx >> 5, c = idx & 31;
        CP_ASYNC16(sb + (uint32_t)((SMO_XT + row * XTS + c * 4) * 4),
                   gx + (size_t)row * BL + kbase + c * 4);
    }
    #pragma unroll
    for (int i = 0; i < 4; i++) {
        int idx = t + i * 256;                   // 1024 chunks, row=idx>>4, c=idx&15
        int row = idx >> 4, c = idx & 15;
        CP_ASYNC16(sb + (uint32_t)((SMO_EST + row * ETS + c * 4) * 4),
                   ge + (size_t)row * Mm + c * 4);
    }
    CP_COMMIT();
    #pragma unroll
    for (int i = 0; i < 4; i++) {
        int idx = t + i * 256;
        int row = idx >> 4, c = idx & 15;
        CP_ASYNC16(sb + (uint32_t)((SMO_EST + 64 * ETS + row * ETS + c * 4) * 4),
                   ge + (size_t)row * Mm + 64 + c * 4);
    }
    CP_COMMIT();

    #pragma unroll
    for (int i = 0; i < 4; i++) ens[t + i * 256] = g_enorm[n * Mm + t + i * 256];
    if (t < 128) xnr[t] = g_xnorm[(size_t)n * BL + kbase + t];

    unsigned long long kreg[16];
    #pragma unroll
    for (int i = 0; i < 16; i++) kreg[i] = 0xFFFFFFFFFFFFFFFFULL;

    CP_WAIT(1);                                  // xt + tile0 resident
    __syncthreads();

    for (int mt = 0; mt < 16; mt++) {
        const float* est = smf + SMO_EST + (mt & 1) * 64 * ETS;
        const int m0base = mt * 64;

        unsigned long long acc[8][2];
        #pragma unroll
        for (int p = 0; p < 8; p++) { acc[p][0] = 0ULL; acc[p][1] = 0ULL; }

        #pragma unroll 4
        for (int d = 0; d < 64; d++) {
            const ulonglong2* xr = (const ulonglong2*)&xt[d * XTS + ty * 16];
            ulonglong2 xa = xr[0], xb = xr[1], xc = xr[2], xd_ = xr[3];
            unsigned long long xp[8] = {xa.x, xa.y, xb.x, xb.y, xc.x, xc.y, xd_.x, xd_.y};
            float2 e2 = *(const float2*)&est[d * ETS + tx * 2];
            unsigned long long ee0, ee1;
            DUP2(ee0, e2.x); DUP2(ee1, e2.y);
            #pragma unroll
            for (int p = 0; p < 8; p++) {
                FMA2(acc[p][0], xp[p], ee0);
                FMA2(acc[p][1], xp[p], ee1);
            }
        }

        // fold: per k-row pick best of this thread's 2 m (exact score, tie->low m)
        float2 se2 = *(const float2*)&ens[m0base + tx * 2];
        const int m0 = m0base + tx * 2;
        #pragma unroll
        for (int p = 0; p < 8; p++) {
            #pragma unroll
            for (int h = 0; h < 2; h++) {
                int rloc = p * 2 + h;
                float Sx = xnr[ty * 16 + rloc];
                uint32_t b0 = h ? (uint32_t)(acc[p][0] >> 32) : (uint32_t)acc[p][0];
                uint32_t b1 = h ? (uint32_t)(acc[p][1] >> 32) : (uint32_t)acc[p][1];
                float s0 = __fadd_rn(__fadd_rn(Sx, se2.x), __fmul_rn(-2.f, __uint_as_float(b0)));
                float s1 = __fadd_rn(__fadd_rn(Sx, se2.y), __fmul_rn(-2.f, __uint_as_float(b1)));
                float bv; int bm;
                if (s1 < s0) { bv = s1; bm = m0 + 1; } else { bv = s0; bm = m0; }
                uint32_t fb = __float_as_uint(bv);
                fb ^= ((uint32_t)((int32_t)fb >> 31)) | 0x80000000u;   // monotone flip
                unsigned long long key = ((unsigned long long)fb << 32) | (uint32_t)bm;
                kreg[rloc] = minull(kreg[rloc], key);
            }
        }

        __syncthreads();                          // all done reading est buffer mt&1
        if (mt < 15) {
            if (mt < 14) {
                const float* gm = ge + (mt + 2) * 64;
                uint32_t db = sb + (uint32_t)((SMO_EST + (mt & 1) * 64 * ETS) * 4);
                #pragma unroll
                for (int i = 0; i < 4; i++) {
                    int idx = t + i * 256;
                    int row = idx >> 4, c = idx & 15;
                    CP_ASYNC16(db + (uint32_t)((row * ETS + c * 4) * 4),
                               gm + (size_t)row * Mm + c * 4);
                }
                CP_COMMIT();
                CP_WAIT(1);                       // tile mt+1 resident
            } else {
                CP_WAIT(0);
            }
            __syncthreads();
        }
    }

    // final: butterfly min over the 32 tx lanes (key64 min = exact argmin)
    #pragma unroll
    for (int r = 0; r < 16; r++) {
        unsigned long long k = kreg[r];
        #pragma unroll
        for (int off = 16; off > 0; off >>= 1)
            k = minull(k, __shfl_xor_sync(0xffffffffu, k, off));
        if (tx == 0) {
            int bidx = (int)(uint32_t)k;
            int kg = kbase + ty * 16 + r;
            g_idx[n * BL + kg] = bidx;
            atomicAdd(&g_cnt[n * Mm + bidx], 1);
            out[OFF_IDX + ((long long)(kg >> 4) * Nn + n) * Ll + (kg & 15)] = (float)bidx;
        }
    }
}

// ---------------------------------------------------------------------------
__global__ void k_dw() {
    int gw = (blockIdx.x * blockDim.x + threadIdx.x) >> 5;
    int lane = threadIdx.x & 31;
    if (gw >= Nn * BL) return;
    int n = gw >> 16;
    int m = g_idx[gw];
    const float* xr = g_xt + (size_t)gw * 64;
    float* dwp = g_dw + ((size_t)n * Mm + m) * 64;
    atomicAdd(dwp + lane,      xr[lane]);
    atomicAdd(dwp + lane + 32, xr[lane + 32]);
}

// ---------------------------------------------------------------------------
__global__ void k_ema(const float* __restrict__ ema_count, float* __restrict__ out) {
    __shared__ float red[1024];
    int t = threadIdx.x;
    float perp = 0.0f;
    for (int n = 0; n < 4; n++) {
        float c = (float)g_cnt[n * Mm + t];
        float raw = DECAYF * ema_count[n * Mm + t] + (1.0f - DECAYF) * c;
        red[t] = raw; __syncthreads();
        for (int s = 512; s > 0; s >>= 1) { if (t < s) red[t] += red[t + s]; __syncthreads(); }
        float nsum = red[0]; __syncthreads();
        float fin = (raw + EPSF) / (nsum + Mm * EPSF) * nsum;
        out[OFF_CNT + n * Mm + t] = fin;
        g_fcnt[n * Mm + t] = fin;
        float avg = c * (1.0f / 65536.0f);
        float term = avg * logf(avg + 1e-10f);
        red[t] = term; __syncthreads();
        for (int s = 512; s > 0; s >>= 1) { if (t < s) red[t] += red[t + s]; __syncthreads(); }
        if (t == 0) perp += expf(-red[0]);
        __syncthreads();
    }
    if (t == 0) out[OFF_PERP] = perp;
}

// ---------------------------------------------------------------------------
__global__ void k_weight(const float* __restrict__ ema_weight, float* __restrict__ out) {
    int i = blockIdx.x * 256 + threadIdx.x;
    float w = DECAYF * ema_weight[i] + (1.0f - DECAYF) * g_dw[i];
    out[OFF_EMW + i] = w;
    out[OFF_EMB + i] = w / g_fcnt[i >> 6];
}

// ---------------------------------------------------------------------------
__global__ void k_gather(const float* __restrict__ x, const float* __restrict__ emb,
                         float* __restrict__ out) {
    __shared__ float se[16][68];
    __shared__ float red[256];
    int bn = blockIdx.x;
    int b = bn >> 2, n = bn & 3;
    int t = threadIdx.x;
    int r = t >> 4, c = t & 15;
    int idx = g_idx[n * BL + b * 16 + r];
    const float4* ep = (const float4*)emb + ((size_t)n * Mm + idx) * 16;
    float4 v = ep[c];
    se[r][c * 4] = v.x; se[r][c * 4 + 1] = v.y; se[r][c * 4 + 2] = v.z; se[r][c * 4 + 3] = v.w;
    __syncthreads();
    long long base = (long long)b * 4096 + n * 1024;
    float4 xv = ((const float4*)(x + base))[t];
    int lin = t * 4;
    int d = lin >> 4, l0 = lin & 15;
    float q0 = se[l0 + 0][d], q1 = se[l0 + 1][d], q2 = se[l0 + 2][d], q3 = se[l0 + 3][d];
    ((float4*)(out + OFF_ZQ + base))[t] = make_float4(q0, q1, q2, q3);
    float2* ez = (float2*)(out + OFF_EZQ + base);
    ez[2 * t]     = make_float2(q0, q1);
    ez[2 * t + 1] = make_float2(q2, q3);
    float d0 = xv.x - q0, d1 = xv.y - q1, d2 = xv.z - q2, d3 = xv.w - q3;
    red[t] = d0 * d0 + d1 * d1 + d2 * d2 + d3 * d3;
    __syncthreads();
    for (int s = 128; s > 0; s >>= 1) { if (t < s) red[t] += red[t + s]; __syncthreads(); }
    if (t == 0) g_losspart[bn] = red[0];
}

// ---------------------------------------------------------------------------
__global__ void k_loss(float* __restrict__ out) {
    __shared__ float red[1024];
    int t = threadIdx.x;
    float s = 0.0f;
    for (int i = t; i < Bb * Nn; i += 1024) s += g_losspart[i];
    red[t] = s; __syncthreads();
    for (int st = 512; st > 0; st >>= 1) { if (t < st) red[t] += red[t + st]; __syncthreads(); }
    if (t == 0) out[OFF_LOSS] = COMMITF * red[0] / 16777216.0f;
}

// ---------------------------------------------------------------------------
extern "C" void kernel_launch(void* const* d_in, const int* in_sizes, int n_in,
                              void* d_out, int out_size) {
    const float* x          = (const float*)d_in[0];
    const float* emb        = (const float*)d_in[1];
    const float* ema_count  = (const float*)d_in[2];
    const float* ema_weight = (const float*)d_in[3];
    float* out = (float*)d_out;

    cudaFuncSetAttribute(k_argmin, cudaFuncAttributeMaxDynamicSharedMemorySize, SM_BYTES);

    k_zero<<<1024, 256>>>();
    k_transpose<<<Bb * Nn, 256>>>(x);
    k_enorm<<<16, 256>>>(emb);
    dim3 ge(16, 4);
    k_et<<<ge, 256>>>(emb);
    dim3 ga(BL / 128, Nn);
    k_argmin<<<ga, 256, SM_BYTES>>>(out);
    k_dw<<<(Nn * BL) / 8, 256>>>();
    k_ema<<<1, 1024>>>(ema_count, out);
    k_weight<<<1024, 256>>>(ema_weight, out);
    k_gather<<<Bb * Nn, 256>>>(x, emb, out);
    k_loss<<<1, 1024>>>(out);
}

// round 12
// speedup vs baseline: 1.0485x; 1.0485x over previous
#include <cuda_runtime.h>
#include <cstdint>

#define Nn 4
#define Mm 1024
#define Dd 64
#define Ll 16
#define Bb 4096
#define BL 65536
#define DECAYF 0.999f
#define EPSF 1e-5f
#define COMMITF 0.05f

#define OFF_ZQ   0LL
#define OFF_LOSS 16777216LL
#define OFF_PERP 16777217LL
#define OFF_IDX  16777218LL
#define OFF_EZQ  17039362LL
#define OFF_EMB  33816578LL
#define OFF_CNT  34078722LL
#define OFF_EMW  34082818LL

__device__ float g_xt[Nn * BL * Dd];      // x (n, k, d) row-major
__device__ float g_xtT[Nn * Dd * BL];     // x transposed (n, d, k)
__device__ float g_etT[Nn * Dd * Mm];     // embedding transposed (n, d, m)
__device__ float g_xnorm[Nn * BL];
__device__ int   g_idx[Nn * BL];
__device__ float g_dw[Nn * Mm * Dd];
__device__ int   g_cnt[Nn * Mm];
__device__ float g_enorm[Nn * Mm];
__device__ float g_fcnt[Nn * Mm];
__device__ float g_losspart[Bb * Nn];

#define CP_ASYNC16(dst, src) \
    asm volatile("cp.async.cg.shared.global [%0], [%1], 16;" :: "r"(dst), "l"(src))
#define CP_COMMIT() asm volatile("cp.async.commit_group;" ::: "memory")
#define CP_WAIT(nconst) asm volatile("cp.async.wait_group %0;" :: "n"(nconst) : "memory")

// packed dual-fp32 FMA (each lane IEEE fp32 -> bit-exact per-element chain)
#define FMA2(acc, a, b) \
    asm("fma.rn.f32x2 %0, %1, %2, %0;" : "+l"(acc) : "l"(a), "l"(b))
#define DUP2(dst, f) \
    asm("mov.b64 %0, {%1, %1};" : "=l"(dst) : "r"(__float_as_uint(f)))

__device__ __forceinline__ uint32_t smem_u32(const void* p) {
    uint32_t a;
    asm("{ .reg .u64 t; cvta.to.shared.u64 t, %1; cvt.u32.u64 %0, t; }" : "=r"(a) : "l"(p));
    return a;
}
__device__ __forceinline__ unsigned long long minull(unsigned long long a, unsigned long long b) {
    return a < b ? a : b;
}

// ---------------------------------------------------------------------------
__global__ void k_zero() {
    int i = blockIdx.x * 256 + threadIdx.x;
    if (i < Nn * Mm * Dd) g_dw[i] = 0.0f;
    if (i < Nn * Mm)      g_cnt[i] = 0;
}

// ---------------------------------------------------------------------------
// Transpose x -> g_xt (row-major) + g_xtT (d-major); ||x||^2 reference-rounded.
__global__ void k_transpose(const float* __restrict__ x) {
    __shared__ float s[16][65];
    int bn = blockIdx.x;
    int b = bn >> 2, n = bn & 3;
    int t = threadIdx.x;
    const float4* xp = (const float4*)(x + (long long)b * 4096 + n * 1024);
    float4 v = xp[t];
    int d = t >> 2, lb = (t & 3) * 4;
    s[lb + 0][d] = v.x; s[lb + 1][d] = v.y; s[lb + 2][d] = v.z; s[lb + 3][d] = v.w;
    __syncthreads();
    int r = t >> 4, c = t & 15;
    float4 w = make_float4(s[r][c * 4], s[r][c * 4 + 1], s[r][c * 4 + 2], s[r][c * 4 + 3]);
    size_t row = (size_t)n * BL + b * 16 + r;
    ((float4*)g_xt)[row * 16 + c] = w;
    int dd = t >> 2, l4 = (t & 3) * 4;
    size_t tb = ((size_t)n * 64 + dd) * BL + b * 16 + l4;
    g_xtT[tb + 0] = s[l4 + 0][dd];
    g_xtT[tb + 1] = s[l4 + 1][dd];
    g_xtT[tb + 2] = s[l4 + 2][dd];
    g_xtT[tb + 3] = s[l4 + 3][dd];
    if (t < 16) {
        float acc = 0.0f;
        #pragma unroll 8
        for (int d2 = 0; d2 < 64; d2++) {
            float vv = s[t][d2];
            acc = __fadd_rn(acc, __fmul_rn(vv, vv));
        }
        g_xnorm[(size_t)n * BL + b * 16 + t] = acc;
    }
}

// ---------------------------------------------------------------------------
__global__ void k_enorm(const float* __restrict__ emb) {
    int i = blockIdx.x * blockDim.x + threadIdx.x;   // 0..4095
    const float* e = emb + (size_t)i * 64;
    float s = 0.0f;
    #pragma unroll 8
    for (int d = 0; d < 64; d++) {
        float v = e[d];
        s = __fadd_rn(s, __fmul_rn(v, v));
    }
    g_enorm[i] = s;
}

// ---------------------------------------------------------------------------
// Embedding transpose: g_etT[n][d][m]. grid (16, 4), 256 thr, 64m x 64d tile.
__global__ void k_et(const float* __restrict__ emb) {
    __shared__ float sm[64][65];
    int n = blockIdx.y, mbase = blockIdx.x * 64;
    int t = threadIdx.x;
    #pragma unroll
    for (int i = 0; i < 16; i++) {
        int idx = t + i * 256;
        sm[idx >> 6][idx & 63] = emb[((size_t)n * Mm + mbase + (idx >> 6)) * 64 + (idx & 63)];
    }
    __syncthreads();
    #pragma unroll
    for (int i = 0; i < 16; i++) {
        int idx = t + i * 256;
        g_etT[((size_t)n * 64 + (idx >> 6)) * Mm + mbase + (idx & 63)] = sm[idx & 63][idx >> 6];
    }
}

// ---------------------------------------------------------------------------
// FFMA2 argmin. 256 threads (tx=t&31 covers 4 m; ty=t>>5 warp owns 16 k-rows).
// CTA: 128 k-rows, 8 m-tiles of 128 codes, double-buffered est prefetch.
// Register argmin keys + warp butterfly. Bit-exact reference score:
//   score = fl( fl(Sx + Se) - 2*dot ), dot = ascending-d fma chain (FMA2 lanes).
#define XTS 132                        // row stride (floats) for xt and est
#define SMO_ENS 0                      // 1024 f
#define SMO_XNR 1024                   // 128 f
#define SMO_XT  1152                   // 64*132 = 8448 f
#define SMO_EST 9600                   // 2 buffers of 64*132 = 16896 f
#define SM_TOTF (9600 + 2 * 64 * XTS)  // 26496 f
#define SM_BYTES (SM_TOTF * 4)         // 105984 B

extern __shared__ float smf[];
__global__ void __launch_bounds__(256, 2)
k_argmin(float* __restrict__ out) {
    const int n = blockIdx.y;
    const int kbase = blockIdx.x * 128;
    const int t = threadIdx.x;
    const int tx = t & 31, ty = t >> 5;
    float* ens = smf + SMO_ENS;
    float* xnr = smf + SMO_XNR;
    float* xt  = smf + SMO_XT;
    uint32_t sb = smem_u32(smf);

    const float* gx = g_xtT + (size_t)n * 64 * BL;
    const float* ge = g_etT + (size_t)n * 64 * Mm;

    // group 0: xt tile (64d x 128k) + est tile 0; group 1: est tile 1
    #pragma unroll
    for (int i = 0; i < 8; i++) {
        int idx = t + i * 256;                   // 2048 chunks: row=idx>>5, c=idx&31
        int row = idx >> 5, c = idx & 31;
        CP_ASYNC16(sb + (uint32_t)((SMO_XT + row * XTS + c * 4) * 4),
                   gx + (size_t)row * BL + kbase + c * 4);
    }
    #pragma unroll
    for (int i = 0; i < 8; i++) {
        int idx = t + i * 256;
        int row = idx >> 5, c = idx & 31;
        CP_ASYNC16(sb + (uint32_t)((SMO_EST + row * XTS + c * 4) * 4),
                   ge + (size_t)row * Mm + c * 4);
    }
    CP_COMMIT();
    #pragma unroll
    for (int i = 0; i < 8; i++) {
        int idx = t + i * 256;
        int row = idx >> 5, c = idx & 31;
        CP_ASYNC16(sb + (uint32_t)((SMO_EST + 64 * XTS + row * XTS + c * 4) * 4),
                   ge + (size_t)row * Mm + 128 + c * 4);
    }
    CP_COMMIT();

    #pragma unroll
    for (int i = 0; i < 4; i++) ens[t + i * 256] = g_enorm[n * Mm + t + i * 256];
    if (t < 128) xnr[t] = g_xnorm[(size_t)n * BL + kbase + t];

    unsigned long long kreg[16];
    #pragma unroll
    for (int i = 0; i < 16; i++) kreg[i] = 0xFFFFFFFFFFFFFFFFULL;

    CP_WAIT(1);                                  // xt + tile0 resident
    __syncthreads();

    for (int mt = 0; mt < 8; mt++) {
        const float* est = smf + SMO_EST + (mt & 1) * 64 * XTS;
        const int mbase = mt * 128;

        unsigned long long acc[8][4];
        #pragma unroll
        for (int p = 0; p < 8; p++)
            #pragma unroll
            for (int j = 0; j < 4; j++) acc[p][j] = 0ULL;

        #pragma unroll 2
        for (int d = 0; d < 64; d++) {
            const ulonglong2* xr = (const ulonglong2*)&xt[d * XTS + ty * 16];
            ulonglong2 xa = xr[0], xb = xr[1], xc = xr[2], xd_ = xr[3];
            unsigned long long xp[8] = {xa.x, xa.y, xb.x, xb.y, xc.x, xc.y, xd_.x, xd_.y};
            float4 e4 = *(const float4*)&est[d * XTS + tx * 4];
            unsigned long long ee[4];
            DUP2(ee[0], e4.x); DUP2(ee[1], e4.y); DUP2(ee[2], e4.z); DUP2(ee[3], e4.w);
            #pragma unroll
            for (int p = 0; p < 8; p++)
                #pragma unroll
                for (int j = 0; j < 4; j++)
                    FMA2(acc[p][j], xp[p], ee[j]);
        }

        // fold: per k-row, best of this thread's 4 m (exact score, ascending m,
        // strict '<' keeps lowest) -> packed sortable key -> register min-merge.
        float4 se4 = *(const float4*)&ens[mbase + tx * 4];
        float se[4] = {se4.x, se4.y, se4.z, se4.w};
        #pragma unroll
        for (int p = 0; p < 8; p++) {
            #pragma unroll
            for (int h = 0; h < 2; h++) {
                int rloc = p * 2 + h;
                float Sx = xnr[ty * 16 + rloc];
                float bestv = 3.4e38f; int bestm = 0;
                #pragma unroll
                for (int j = 0; j < 4; j++) {
                    uint32_t bits = h ? (uint32_t)(acc[p][j] >> 32) : (uint32_t)acc[p][j];
                    float dot = __uint_as_float(bits);
                    float sc = __fadd_rn(__fadd_rn(Sx, se[j]), __fmul_rn(-2.0f, dot));
                    if (sc < bestv) { bestv = sc; bestm = mbase + tx * 4 + j; }
                }
                uint32_t fb = __float_as_uint(bestv);
                fb ^= ((uint32_t)((int32_t)fb >> 31)) | 0x80000000u;   // monotone flip
                unsigned long long key = ((unsigned long long)fb << 32) | (uint32_t)bestm;
                kreg[rloc] = minull(kreg[rloc], key);
            }
        }

        __syncthreads();                          // reads of est buffer mt&1 done
        if (mt < 7) {
            if (mt < 6) {
                const float* gm = ge + (mt + 2) * 128;
                uint32_t db = sb + (uint32_t)((SMO_EST + (mt & 1) * 64 * XTS) * 4);
                #pragma unroll
                for (int i = 0; i < 8; i++) {
                    int idx = t + i * 256;
                    int row = idx >> 5, c = idx & 31;
                    CP_ASYNC16(db + (uint32_t)((row * XTS + c * 4) * 4),
                               gm + (size_t)row * Mm + c * 4);
                }
                CP_COMMIT();
                CP_WAIT(1);                       // tile mt+1 resident
            } else {
                CP_WAIT(0);
            }
            __syncthreads();
        }
    }

    // final: butterfly min over the 32 tx lanes (key64 min = exact argmin, tie->low m)
    #pragma unroll
    for (int r = 0; r < 16; r++) {
        unsigned long long k = kreg[r];
        #pragma unroll
        for (int off = 16; off > 0; off >>= 1)
            k = minull(k, __shfl_xor_sync(0xffffffffu, k, off));
        if (tx == 0) {
            int bidx = (int)(uint32_t)k;
            int kg = kbase + ty * 16 + r;
            g_idx[n * BL + kg] = bidx;
            atomicAdd(&g_cnt[n * Mm + bidx], 1);
            out[OFF_IDX + ((long long)(kg >> 4) * Nn + n) * Ll + (kg & 15)] = (float)bidx;
        }
    }
}

// ---------------------------------------------------------------------------
__global__ void k_dw() {
    int gw = (blockIdx.x * blockDim.x + threadIdx.x) >> 5;
    int lane = threadIdx.x & 31;
    if (gw >= Nn * BL) return;
    int n = gw >> 16;
    int m = g_idx[gw];
    const float* xr = g_xt + (size_t)gw * 64;
    float* dwp = g_dw + ((size_t)n * Mm + m) * 64;
    atomicAdd(dwp + lane,      xr[lane]);
    atomicAdd(dwp + lane + 32, xr[lane + 32]);
}

// ---------------------------------------------------------------------------
__global__ void k_ema(const float* __restrict__ ema_count, float* __restrict__ out) {
    __shared__ float red[1024];
    int t = threadIdx.x;
    float perp = 0.0f;
    for (int n = 0; n < 4; n++) {
        float c = (float)g_cnt[n * Mm + t];
        float raw = DECAYF * ema_count[n * Mm + t] + (1.0f - DECAYF) * c;
        red[t] = raw; __syncthreads();
        for (int s = 512; s > 0; s >>= 1) { if (t < s) red[t] += red[t + s]; __syncthreads(); }
        float nsum = red[0]; __syncthreads();
        float fin = (raw + EPSF) / (nsum + Mm * EPSF) * nsum;
        out[OFF_CNT + n * Mm + t] = fin;
        g_fcnt[n * Mm + t] = fin;
        float avg = c * (1.0f / 65536.0f);
        float term = avg * logf(avg + 1e-10f);
        red[t] = term; __syncthreads();
        for (int s = 512; s > 0; s >>= 1) { if (t < s) red[t] += red[t + s]; __syncthreads(); }
        if (t == 0) perp += expf(-red[0]);
        __syncthreads();
    }
    if (t == 0) out[OFF_PERP] = perp;
}

// ---------------------------------------------------------------------------
__global__ void k_weight(const float* __restrict__ ema_weight, float* __restrict__ out) {
    int i = blockIdx.x * 256 + threadIdx.x;
    float w = DECAYF * ema_weight[i] + (1.0f - DECAYF) * g_dw[i];
    out[OFF_EMW + i] = w;
    out[OFF_EMB + i] = w / g_fcnt[i >> 6];
}

// ---------------------------------------------------------------------------
__global__ void k_gather(const float* __restrict__ x, const float* __restrict__ emb,
                         float* __restrict__ out) {
    __shared__ float se[16][68];
    __shared__ float red[256];
    int bn = blockIdx.x;
    int b = bn >> 2, n = bn & 3;
    int t = threadIdx.x;
    int r = t >> 4, c = t & 15;
    int idx = g_idx[n * BL + b * 16 + r];
    const float4* ep = (const float4*)emb + ((size_t)n * Mm + idx) * 16;
    float4 v = ep[c];
    se[r][c * 4] = v.x; se[r][c * 4 + 1] = v.y; se[r][c * 4 + 2] = v.z; se[r][c * 4 + 3] = v.w;
    __syncthreads();
    long long base = (long long)b * 4096 + n * 1024;
    float4 xv = ((const float4*)(x + base))[t];
    int lin = t * 4;
    int d = lin >> 4, l0 = lin & 15;
    float q0 = se[l0 + 0][d], q1 = se[l0 + 1][d], q2 = se[l0 + 2][d], q3 = se[l0 + 3][d];
    ((float4*)(out + OFF_ZQ + base))[t] = make_float4(q0, q1, q2, q3);
    float2* ez = (float2*)(out + OFF_EZQ + base);
    ez[2 * t]     = make_float2(q0, q1);
    ez[2 * t + 1] = make_float2(q2, q3);
    float d0 = xv.x - q0, d1 = xv.y - q1, d2 = xv.z - q2, d3 = xv.w - q3;
    red[t] = d0 * d0 + d1 * d1 + d2 * d2 + d3 * d3;
    __syncthreads();
    for (int s = 128; s > 0; s >>= 1) { if (t < s) red[t] += red[t + s]; __syncthreads(); }
    if (t == 0) g_losspart[bn] = red[0];
}

// ---------------------------------------------------------------------------
__global__ void k_loss(float* __restrict__ out) {
    __shared__ float red[1024];
    int t = threadIdx.x;
    float s = 0.0f;
    for (int i = t; i < Bb * Nn; i += 1024) s += g_losspart[i];
    red[t] = s; __syncthreads();
    for (int st = 512; st > 0; st >>= 1) { if (t < st) red[t] += red[t + st]; __syncthreads(); }
    if (t == 0) out[OFF_LOSS] = COMMITF * red[0] / 16777216.0f;
}

// ---------------------------------------------------------------------------
extern "C" void kernel_launch(void* const* d_in, const int* in_sizes, int n_in,
                              void* d_out, int out_size) {
    const float* x          = (const float*)d_in[0];
    const float* emb        = (const float*)d_in[1];
    const float* ema_count  = (const float*)d_in[2];
    const float* ema_weight = (const float*)d_in[3];
    float* out = (float*)d_out;

    cudaFuncSetAttribute(k_argmin, cudaFuncAttributeMaxDynamicSharedMemorySize, SM_BYTES);

    k_zero<<<1024, 256>>>();
    k_transpose<<<Bb * Nn, 256>>>(x);
    k_enorm<<<16, 256>>>(emb);
    dim3 ge(16, 4);
    k_et<<<ge, 256>>>(emb);
    dim3 ga(BL / 128, Nn);
    k_argmin<<<ga, 256, SM_BYTES>>>(out);
    k_dw<<<(Nn * BL) / 8, 256>>>();
    k_ema<<<1, 1024>>>(ema_count, out);
    k_weight<<<1024, 256>>>(ema_weight, out);
    k_gather<<<Bb * Nn, 256>>>(x, emb, out);
    k_loss<<<1, 1024>>>(out);
}